// round 3
// baseline (speedup 1.0000x reference)
#include <cuda_runtime.h>
#include <cstdint>

// ChebyshevEncoder: x [B=16, N=65536, D=2] fp32 -> out [B, N, D*ORDER] fp32
// out[p*60 + d*30 + m] = T_m(x[p][d]) for pair p = b*N+n.
//
// R3: persistent blocks, double-buffered smem staging, per-chunk
// cp.async.bulk smem->global, and crucially wait_group.READ (smem reuse
// only) instead of full completion -> TMA writes drain off the critical
// path and the bulk engine is continuously fed.

#define ORDER 30
#define TPB   128
#define CHUNK 128                         // pairs per chunk == TPB
#define BYTES_PER_PAIR 240                // 60 floats
#define CHUNK_BYTES  (CHUNK * BYTES_PER_PAIR)   // 30720
#define CHUNK_FLOATS (CHUNK_BYTES / 4)          // 7680
#define SMEM_BYTES   (2 * CHUNK_BYTES)          // 61440

__device__ __forceinline__ uint32_t smem_u32(const void* p) {
    uint32_t a;
    asm("{ .reg .u64 t; cvta.to.shared.u64 t, %1; cvt.u32.u64 %0, t; }"
        : "=r"(a) : "l"(p));
    return a;
}

extern __shared__ __align__(16) float sbuf[];   // 2 * CHUNK_FLOATS

__global__ __launch_bounds__(TPB) void cheb_kernel(
    const float2* __restrict__ x,
    float* __restrict__ out,
    int npairs, int nchunks)
{
    const int t = threadIdx.x;

    int it = 0;
    for (int c = blockIdx.x; c < nchunks; c += gridDim.x, ++it) {
        float* buf = sbuf + (it & 1) * CHUNK_FLOATS;

        // Free the buffer issued 2 iterations ago (read-complete is enough
        // for smem reuse; global writes drain asynchronously).
        if (it >= 2 && t == 0)
            asm volatile("cp.async.bulk.wait_group.read 1;" ::: "memory");
        __syncthreads();   // all threads see buffer as free

        const int blockPair = c * CHUNK;
        const int p = blockPair + t;

        if (p < npairs) {
            const float2 xv = __ldg(&x[p]);

            float T[60];
            {
                const float xx = xv.x;
                T[0] = 1.0f;
                T[1] = xx;
#pragma unroll
                for (int m = 2; m < ORDER; m++)
                    T[m] = 2.0f * xx * T[m - 1] - T[m - 2];
            }
            {
                const float xx = xv.y;
                T[ORDER + 0] = 1.0f;
                T[ORDER + 1] = xx;
#pragma unroll
                for (int m = 2; m < ORDER; m++)
                    T[ORDER + m] = 2.0f * xx * T[ORDER + m - 1] - T[ORDER + m - 2];
            }

            // 15 STS.128 at 16B-unit address 15*t + c: conflict-free within
            // each quarter-warp (15t mod 8 is a bijection), no padding.
            float4* dst = reinterpret_cast<float4*>(&buf[t * 60]);
            const float4* src = reinterpret_cast<const float4*>(T);
#pragma unroll
            for (int k = 0; k < 15; k++)
                dst[k] = src[k];
        }
        __syncthreads();   // all STS done before async-proxy read

        if (t == 0) {
            int cnt = npairs - blockPair;
            if (cnt > CHUNK) cnt = CHUNK;
            if (cnt > 0) {
                const uint32_t sbytes = (uint32_t)cnt * BYTES_PER_PAIR;
                const uint32_t saddr  = smem_u32(buf);
                float* gdst = out + (size_t)blockPair * 60;

                asm volatile("fence.proxy.async.shared::cta;" ::: "memory");
                asm volatile(
                    "cp.async.bulk.global.shared::cta.bulk_group [%0], [%1], %2;"
                    :: "l"(gdst), "r"(saddr), "r"(sbytes)
                    : "memory");
                asm volatile("cp.async.bulk.commit_group;" ::: "memory");
            }
        }
    }

    // Safe CTA exit: fully drain this thread's bulk groups once per block.
    if (t == 0)
        asm volatile("cp.async.bulk.wait_group 0;" ::: "memory");
}

extern "C" void kernel_launch(void* const* d_in, const int* in_sizes, int n_in,
                              void* d_out, int out_size)
{
    (void)n_in; (void)out_size;
    const float2* x = (const float2*)d_in[0];
    float* out = (float*)d_out;

    const int nelem   = in_sizes[0];          // B*N*D floats
    const int npairs  = nelem / 2;            // B*N pairs (D=2)
    const int nchunks = (npairs + CHUNK - 1) / CHUNK;

    static_assert(SMEM_BYTES == 61440, "smem layout");
    cudaFuncSetAttribute(cheb_kernel,
                         cudaFuncAttributeMaxDynamicSharedMemorySize, SMEM_BYTES);

    int dev = 0, nsm = 148;
    cudaGetDevice(&dev);
    cudaDeviceGetAttribute(&nsm, cudaDevAttrMultiProcessorCount, dev);

    int grid = 3 * nsm;                       // 3 blocks/SM (61.4KB smem each)
    if (grid > nchunks) grid = nchunks;

    cheb_kernel<<<grid, TPB, SMEM_BYTES>>>(x, out, npairs, nchunks);
}

// round 4
// speedup vs baseline: 1.1158x; 1.1158x over previous
#include <cuda_runtime.h>
#include <cstdint>

// ChebyshevEncoder: x [B=16, N=65536, D=2] fp32 -> out [B, N, D*ORDER] fp32
// out[p*60 + d*30 + m] = T_m(x[p][d]) for pair p = b*N+n.
//
// R4: non-persistent grid (8192 CTAs) for natural churn concurrency.
// Each WARP owns 32 pairs = one contiguous 7680B smem region = one
// contiguous output region. Warp computes -> syncwarp -> lane 0 fences +
// issues cp.async.bulk for its own region -> wait_group.READ 0 -> retire.
// No __syncthreads; CTA exit waits only on the TMA smem READ, global
// writes drain after exit.

#define ORDER 30
#define TPB   128
#define PAIRS_PER_WARP 32
#define WARP_FLOATS (PAIRS_PER_WARP * 60)        // 1920 floats
#define WARP_BYTES  (WARP_FLOATS * 4)            // 7680 B

__device__ __forceinline__ uint32_t smem_u32(const void* p) {
    uint32_t a;
    asm("{ .reg .u64 t; cvta.to.shared.u64 t, %1; cvt.u32.u64 %0, t; }"
        : "=r"(a) : "l"(p));
    return a;
}

__global__ __launch_bounds__(TPB) void cheb_kernel(
    const float2* __restrict__ x,
    float* __restrict__ out,
    int npairs)
{
    __shared__ __align__(16) float s[TPB * 60];  // 30720 B, output order

    const int t    = threadIdx.x;
    const int w    = t >> 5;
    const int lane = t & 31;
    const int blockPair = blockIdx.x * TPB;
    const int warpPair  = blockPair + w * PAIRS_PER_WARP;
    const int p = warpPair + lane;

    float* wbuf = s + w * WARP_FLOATS;

    if (p < npairs) {
        const float2 xv = __ldg(&x[p]);

        float T[60];
        {
            const float xx = xv.x;
            T[0] = 1.0f;
            T[1] = xx;
#pragma unroll
            for (int m = 2; m < ORDER; m++)
                T[m] = 2.0f * xx * T[m - 1] - T[m - 2];
        }
        {
            const float xx = xv.y;
            T[ORDER + 0] = 1.0f;
            T[ORDER + 1] = xx;
#pragma unroll
            for (int m = 2; m < ORDER; m++)
                T[ORDER + m] = 2.0f * xx * T[ORDER + m - 1] - T[ORDER + m - 2];
        }

        // 15 STS.128, 16B-unit addr = 15*lane + k: conflict-free per
        // quarter-warp (15*lane mod 8 is a bijection over 8 lanes).
        float4* dst = reinterpret_cast<float4*>(&wbuf[lane * 60]);
        const float4* src = reinterpret_cast<const float4*>(T);
#pragma unroll
        for (int k = 0; k < 15; k++)
            dst[k] = src[k];
    }

    __syncwarp();

    if (lane == 0 && warpPair < npairs) {
        int cnt = npairs - warpPair;
        if (cnt > PAIRS_PER_WARP) cnt = PAIRS_PER_WARP;

        const uint32_t sbytes = (uint32_t)cnt * 240u;
        const uint32_t saddr  = smem_u32(wbuf);
        float* gdst = out + (size_t)warpPair * 60;

        // Make the warp's generic-proxy STS visible to the async proxy.
        asm volatile("fence.proxy.async.shared::cta;" ::: "memory");
        asm volatile(
            "cp.async.bulk.global.shared::cta.bulk_group [%0], [%1], %2;"
            :: "l"(gdst), "r"(saddr), "r"(sbytes)
            : "memory");
        asm volatile("cp.async.bulk.commit_group;" ::: "memory");
        // Exit-safe as soon as the bulk engine has READ smem; the global
        // writes drain after CTA exit.
        asm volatile("cp.async.bulk.wait_group.read 0;" ::: "memory");
    }
}

extern "C" void kernel_launch(void* const* d_in, const int* in_sizes, int n_in,
                              void* d_out, int out_size)
{
    (void)n_in; (void)out_size;
    const float2* x = (const float2*)d_in[0];
    float* out = (float*)d_out;

    const int nelem  = in_sizes[0];      // B*N*D floats
    const int npairs = nelem / 2;        // B*N pairs (D=2)
    const int blocks = (npairs + TPB - 1) / TPB;

    cheb_kernel<<<blocks, TPB>>>(x, out, npairs);
}